// round 8
// baseline (speedup 1.0000x reference)
#include <cuda_runtime.h>

// ForwardKinematics: B=65536, N=24.
// R7: float4-native smem layout to cut LDS wavefronts 3x.
//  sR: [MB] x [NJ][3 rows][4] (joint stride 12 floats, batch stride 292 floats
//      = 73 x 16B, odd -> conflict-free LDS.128 across the 8 batches of a warp)
//  sJ: [MB] x [NJ][4] (batch stride 100 floats = 25 x 16B, odd)
//  Phase B: 5 LDS.128 per joint (3 R rows + j[i] + j[parent]); rel row stored
//  straight to gmem (r==3 lanes store (0,0,0,1)); posed joints stored scalar
//  from the same lane. No phase C, single __syncwarp.

#define THREADS 128
#define MB 32            // batches per block (8 per warp)
#define BPW 8            // batches per warp

static constexpr int NJ    = 24;
static constexpr int RSTR  = 292;   // floats per batch in sR (288 used + 4 pad), 73*16B
static constexpr int JSTR  = 100;   // floats per batch in sJ (96 used + 4 pad), 25*16B
static constexpr int SMEM_FLOATS = MB * (RSTR + JSTR);
static constexpr int SMEM_BYTES  = SMEM_FLOATS * 4;   // 50176 B -> 4 CTAs/SM

__global__ __launch_bounds__(THREADS)
void fk_kernel(const float* __restrict__ rot,
               const float* __restrict__ jnt,
               float* __restrict__ out_pj,
               float* __restrict__ out_rel)
{
    extern __shared__ float sm[];
    float* sR = sm;                    // [MB][RSTR]
    float* sJ = sR + MB * RSTR;        // [MB][JSTR]

    const int tid  = threadIdx.x;
    const int warp = tid >> 5;
    const int lane = tid & 31;
    const int wb   = warp * BPW;
    const long long gBatch = (long long)blockIdx.x * MB + wb;

    // ---------------- Phase A: coalesced loads, scatter into padded layout ----------------
    {
        const float4* rot4 = reinterpret_cast<const float4*>(rot) + gBatch * 54;
        #pragma unroll
        for (int it = 0; it < 14; ++it) {              // 8*54 = 432 float4
            int idx = lane + it * 32;
            if (idx < BPW * 54) {
                float4 v = rot4[idx];
                int b  = wb + idx / 54;
                int e0 = (idx % 54) * 4;
                float* base = sR + b * RSTR;
                float vv[4] = {v.x, v.y, v.z, v.w};
                #pragma unroll
                for (int k = 0; k < 4; ++k) {
                    int e  = e0 + k;
                    int jt = e / 9, m = e % 9;
                    base[jt * 12 + (m / 3) * 4 + (m % 3)] = vv[k];
                }
            }
        }
        const float4* jnt4 = reinterpret_cast<const float4*>(jnt) + gBatch * 18;
        #pragma unroll
        for (int it = 0; it < 5; ++it) {               // 8*18 = 144 float4
            int idx = lane + it * 32;
            if (idx < BPW * 18) {
                float4 v = jnt4[idx];
                int b  = wb + idx / 18;
                int e0 = (idx % 18) * 4;
                float* base = sJ + b * JSTR;
                float vv[4] = {v.x, v.y, v.z, v.w};
                #pragma unroll
                for (int k = 0; k < 4; ++k) {
                    int e  = e0 + k;
                    base[(e / 3) * 4 + (e % 3)] = vv[k];
                }
            }
        }
    }
    __syncwarp();

    // ------- Phase B: chain walk, float4 LDS, direct gmem stores -------
    {
        constexpr int PAR[NJ] = {-1,0,0,0,1,2,3,4,5,6,7,8,9,9,9,12,13,14,16,17,18,19,20,21};
        const int  bl     = lane >> 2;          // 0..7 local batch
        const int  b      = wb + bl;
        const int  r      = lane & 3;
        const bool active = (r < 3);
        float ring[6][4];                       // [slot][Rg_r0,Rg_r1,Rg_r2,t_r]
        const float4* mR4 = reinterpret_cast<const float4*>(sR + b * RSTR);  // 73 f4/batch
        const float4* mJ4 = reinterpret_cast<const float4*>(sJ + b * JSTR);  // 25 f4/batch
        float4* relW = reinterpret_cast<float4*>(out_rel) + (gBatch + bl) * 96;
        float*  pjW  = out_pj + (gBatch + bl) * 72;

        #pragma unroll
        for (int i = 0; i < NJ; ++i) {
            float4 v;
            if (active) {
                float row[4];
                const float4 jv = mJ4[i];
                if (i == 0) {
                    const float4 l = mR4[r];
                    row[0] = l.x; row[1] = l.y; row[2] = l.z;
                    row[3] = (r == 0) ? jv.x : (r == 1) ? jv.y : jv.z;
                } else {
                    const int p  = PAR[i];
                    const int ps = p % 6;
                    const float a0 = ring[ps][0], a1 = ring[ps][1], a2 = ring[ps][2];
                    const float4 l0 = mR4[i * 3 + 0];
                    const float4 l1 = mR4[i * 3 + 1];
                    const float4 l2 = mR4[i * 3 + 2];
                    const float4 pjv = mJ4[p];
                    const float rel0 = jv.x - pjv.x;
                    const float rel1 = jv.y - pjv.y;
                    const float rel2 = jv.z - pjv.z;
                    row[0] = a0 * l0.x + a1 * l1.x + a2 * l2.x;
                    row[1] = a0 * l0.y + a1 * l1.y + a2 * l2.y;
                    row[2] = a0 * l0.z + a1 * l1.z + a2 * l2.z;
                    row[3] = ring[ps][3] + a0 * rel0 + a1 * rel1 + a2 * rel2;
                }
                const int s = i % 6;
                #pragma unroll
                for (int k = 0; k < 4; ++k) ring[s][k] = row[k];
                pjW[i * 3 + r] = row[3];                        // posed joint comp r
                v = make_float4(row[0], row[1], row[2],
                                row[3] - (row[0]*jv.x + row[1]*jv.y + row[2]*jv.z));
            } else {
                v = make_float4(0.f, 0.f, 0.f, 1.f);            // bottom row
            }
            relW[i * 4 + r] = v;                                // rel row
        }
    }
}

extern "C" void kernel_launch(void* const* d_in, const int* in_sizes, int n_in,
                              void* d_out, int out_size)
{
    const float* rot = (const float*)d_in[0];
    const float* jnt = (const float*)d_in[1];
    float* out = (float*)d_out;

    const long long B = 65536;
    float* out_pj  = out;
    float* out_rel = out + (size_t)B * NJ * 3;

    cudaFuncSetAttribute(fk_kernel, cudaFuncAttributeMaxDynamicSharedMemorySize, SMEM_BYTES);

    const int grid = (int)(B / MB);   // 2048 blocks
    fk_kernel<<<grid, THREADS, SMEM_BYTES>>>(rot, jnt, out_pj, out_rel);
}

// round 9
// speedup vs baseline: 1.4880x; 1.4880x over previous
#include <cuda_runtime.h>

// ForwardKinematics: B=65536, N=24.
// R8 = R6 structure + (a) even 16B batch strides so phase A/C use STS.128/LDS.128
//      with cheap indexing, (b) parent-joint register ring (drops 3 LDS/joint),
//      (c) same direct rel STG.128 + coalesced posed-joints copy.
// Bank math: R batch stride 220 -> bank (b*28+r*3+c)%32: 24 distinct -> conflict-free.
//            J batch stride 76  -> bank (b*12+c)%32: distinct -> conflict-free.

#define THREADS 128
#define MB 32            // batches per block (8 per warp)
#define BPW 8            // batches per warp

static constexpr int NJ   = 24;
static constexpr int RSTR = 220;   // 216 + 4 pad floats = 55 x 16B (16B-aligned batches)
static constexpr int JSTR = 76;    // 72 + 4 pad = 19 x 16B
static constexpr int TSTR = 76;    // global t rows, 19 x 16B
static constexpr int SMEM_FLOATS = MB * (RSTR + JSTR + TSTR);
static constexpr int SMEM_BYTES  = SMEM_FLOATS * 4;   // 47616 B -> 4 CTAs/SM

__global__ __launch_bounds__(THREADS)
void fk_kernel(const float* __restrict__ rot,
               const float* __restrict__ jnt,
               float* __restrict__ out_pj,
               float* __restrict__ out_rel)
{
    extern __shared__ float sm[];
    float* sR = sm;                    // [MB][RSTR] local R (read-only after A)
    float* sJ = sR + MB * RSTR;        // [MB][JSTR] absolute joints
    float* sT = sJ + MB * JSTR;        // [MB][TSTR] global t

    const int tid  = threadIdx.x;
    const int warp = tid >> 5;
    const int lane = tid & 31;
    const int wb   = warp * BPW;
    const long long gBatch = (long long)blockIdx.x * MB + wb;

    // ---------------- Phase A: float4 loads -> float4 smem stores ----------------
    {
        float4* sR4 = reinterpret_cast<float4*>(sR);       // batch stride 55 f4
        const float4* rot4 = reinterpret_cast<const float4*>(rot) + gBatch * 54;
        #pragma unroll
        for (int it = 0; it < 14; ++it) {                  // 8*54 = 432 float4
            int idx = lane + it * 32;
            if (idx < BPW * 54) {
                int b = wb + idx / 54, rf = idx % 54;
                sR4[b * 55 + rf] = rot4[idx];
            }
        }
        float4* sJ4 = reinterpret_cast<float4*>(sJ);       // batch stride 19 f4
        const float4* jnt4 = reinterpret_cast<const float4*>(jnt) + gBatch * 18;
        #pragma unroll
        for (int it = 0; it < 5; ++it) {                   // 8*18 = 144 float4
            int idx = lane + it * 32;
            if (idx < BPW * 18) {
                int b = wb + idx / 18, rf = idx % 18;
                sJ4[b * 19 + rf] = jnt4[idx];
            }
        }
    }
    __syncwarp();

    // ------- Phase B: sync-free chain walk, j kept in a register ring -------
    {
        constexpr int PAR[NJ] = {-1,0,0,0,1,2,3,4,5,6,7,8,9,9,9,12,13,14,16,17,18,19,20,21};
        const int  bl     = lane >> 2;          // 0..7 local batch
        const int  b      = wb + bl;
        const int  r      = lane & 3;
        const bool active = (r < 3);
        float ring[6][4];                       // [slot][Rg_r0,Rg_r1,Rg_r2,t_r]
        float jring[6][3];                      // [slot][j0,j1,j2]
        const float* mR = sR + b * RSTR;
        const float* mJ = sJ + b * JSTR;
        float*       mT = sT + b * TSTR;
        float4* relW = reinterpret_cast<float4*>(out_rel) + (gBatch + bl) * 96;

        #pragma unroll
        for (int i = 0; i < NJ; ++i) {
            float4 v;
            if (active) {
                float row[4];
                const float j0 = mJ[i * 3 + 0];
                const float j1 = mJ[i * 3 + 1];
                const float j2 = mJ[i * 3 + 2];
                if (i == 0) {
                    row[0] = mR[r * 3 + 0];
                    row[1] = mR[r * 3 + 1];
                    row[2] = mR[r * 3 + 2];
                    row[3] = (r == 0) ? j0 : (r == 1) ? j1 : j2;
                } else {
                    const int p  = PAR[i];
                    const int ps = p % 6;
                    const float a0 = ring[ps][0], a1 = ring[ps][1], a2 = ring[ps][2];
                    const float l00 = mR[i*9+0], l01 = mR[i*9+1], l02 = mR[i*9+2];
                    const float l10 = mR[i*9+3], l11 = mR[i*9+4], l12 = mR[i*9+5];
                    const float l20 = mR[i*9+6], l21 = mR[i*9+7], l22 = mR[i*9+8];
                    const float rel0 = j0 - jring[ps][0];
                    const float rel1 = j1 - jring[ps][1];
                    const float rel2 = j2 - jring[ps][2];
                    row[0] = a0 * l00 + a1 * l10 + a2 * l20;
                    row[1] = a0 * l01 + a1 * l11 + a2 * l21;
                    row[2] = a0 * l02 + a1 * l12 + a2 * l22;
                    row[3] = ring[ps][3] + a0 * rel0 + a1 * rel1 + a2 * rel2;
                }
                const int s = i % 6;
                #pragma unroll
                for (int k = 0; k < 4; ++k) ring[s][k] = row[k];
                jring[s][0] = j0; jring[s][1] = j1; jring[s][2] = j2;
                mT[i * 3 + r] = row[3];                       // for posed_joints
                v = make_float4(row[0], row[1], row[2],
                                row[3] - (row[0]*j0 + row[1]*j1 + row[2]*j2));
            } else {
                v = make_float4(0.f, 0.f, 0.f, 1.f);          // bottom row
            }
            relW[i * 4 + r] = v;                              // direct rel store
        }
    }
    __syncwarp();

    // ---------------- Phase C: coalesced posed-joints copy (LDS.128) ----------------
    {
        const float4* sT4 = reinterpret_cast<const float4*>(sT);   // batch stride 19 f4
        float4* pj4 = reinterpret_cast<float4*>(out_pj) + gBatch * 18;
        #pragma unroll
        for (int it = 0; it < 5; ++it) {                   // 8*18 = 144 float4
            int idx = lane + it * 32;
            if (idx < BPW * 18) {
                int b = wb + idx / 18, rf = idx % 18;
                pj4[idx] = sT4[b * 19 + rf];
            }
        }
    }
}

extern "C" void kernel_launch(void* const* d_in, const int* in_sizes, int n_in,
                              void* d_out, int out_size)
{
    const float* rot = (const float*)d_in[0];
    const float* jnt = (const float*)d_in[1];
    float* out = (float*)d_out;

    const long long B = 65536;
    float* out_pj  = out;
    float* out_rel = out + (size_t)B * NJ * 3;

    cudaFuncSetAttribute(fk_kernel, cudaFuncAttributeMaxDynamicSharedMemorySize, SMEM_BYTES);

    const int grid = (int)(B / MB);   // 2048 blocks
    fk_kernel<<<grid, THREADS, SMEM_BYTES>>>(rot, jnt, out_pj, out_rel);
}